// round 1
// baseline (speedup 1.0000x reference)
#include <cuda_runtime.h>
#include <math.h>

// Problem constants
#define B_SZ   8
#define N_SEQ  1024
#define C_DIM  768
#define H_HEAD 12
#define D_HEAD 64
#define QKV_LD 2304            // 3*C
#define SCALE  0.125f          // 64^-0.5

// Scratch (allocation-free: __device__ globals)
__device__ float g_qkv[(size_t)B_SZ * N_SEQ * 3 * C_DIM];          // [8192, 2304]  (b,n, s*768+h*64+d)
__device__ float g_scores[(size_t)B_SZ * H_HEAD * N_SEQ * N_SEQ];  // [96, 1024, 1024]
__device__ float g_av[(size_t)B_SZ * N_SEQ * C_DIM];               // [8192, 768]   (b,n, h*64+d)

// ---------------------------------------------------------------------------
// Generic NN GEMM with bias: C[M,N] = A[M,K] @ B[K,N] + bias[N]
// 128x128 block, BK=16, 256 threads, 8x8 per thread. Dims must divide tiles.
// ---------------------------------------------------------------------------
__global__ __launch_bounds__(256) void gemm_nn_bias(
    const float* __restrict__ A, const float* __restrict__ B,
    const float* __restrict__ bias, float* __restrict__ C,
    int K, int lda, int ldb, int ldc)
{
    __shared__ float As[16][128];
    __shared__ float Bs[16][128];
    const int tid = threadIdx.x;
    const int tx = tid & 15, ty = tid >> 4;
    const int row0 = blockIdx.y * 128;
    const int col0 = blockIdx.x * 128;

    float acc[8][8];
#pragma unroll
    for (int i = 0; i < 8; i++)
#pragma unroll
        for (int j = 0; j < 8; j++) acc[i][j] = 0.f;

    for (int k0 = 0; k0 < K; k0 += 16) {
#pragma unroll
        for (int l = 0; l < 2; l++) {
            int f = tid + l * 256;
            int r = f >> 2;
            int cv = (f & 3) << 2;
            float4 v = *reinterpret_cast<const float4*>(A + (size_t)(row0 + r) * lda + k0 + cv);
            As[cv + 0][r] = v.x; As[cv + 1][r] = v.y; As[cv + 2][r] = v.z; As[cv + 3][r] = v.w;
        }
#pragma unroll
        for (int l = 0; l < 2; l++) {
            int f = tid + l * 256;
            int r = f >> 5;
            int cv = (f & 31) << 2;
            *reinterpret_cast<float4*>(&Bs[r][cv]) =
                *reinterpret_cast<const float4*>(B + (size_t)(k0 + r) * ldb + col0 + cv);
        }
        __syncthreads();
#pragma unroll
        for (int k = 0; k < 16; k++) {
            float4 a0 = *reinterpret_cast<const float4*>(&As[k][ty * 8]);
            float4 a1 = *reinterpret_cast<const float4*>(&As[k][ty * 8 + 4]);
            float4 b0 = *reinterpret_cast<const float4*>(&Bs[k][tx * 8]);
            float4 b1 = *reinterpret_cast<const float4*>(&Bs[k][tx * 8 + 4]);
            float a[8] = {a0.x, a0.y, a0.z, a0.w, a1.x, a1.y, a1.z, a1.w};
            float b[8] = {b0.x, b0.y, b0.z, b0.w, b1.x, b1.y, b1.z, b1.w};
#pragma unroll
            for (int i = 0; i < 8; i++)
#pragma unroll
                for (int j = 0; j < 8; j++) acc[i][j] = fmaf(a[i], b[j], acc[i][j]);
        }
        __syncthreads();
    }
#pragma unroll
    for (int i = 0; i < 8; i++) {
        int r = row0 + ty * 8 + i;
#pragma unroll
        for (int j = 0; j < 8; j++) {
            int c = col0 + tx * 8 + j;
            C[(size_t)r * ldc + c] = acc[i][j] + bias[c];
        }
    }
}

// ---------------------------------------------------------------------------
// QK^T: scores[z, n, m] = SCALE * sum_d q[z,n,d] * k[z,m,d], z = b*12+h
// q, k live strided inside g_qkv (lda = 2304). NT GEMM, K=64.
// ---------------------------------------------------------------------------
__global__ __launch_bounds__(256) void qk_kernel()
{
    const int z = blockIdx.z;
    const int b = z / H_HEAD, h = z % H_HEAD;
    const float* Aq = g_qkv + (size_t)b * N_SEQ * QKV_LD + h * D_HEAD;          // q
    const float* Bk = g_qkv + (size_t)b * N_SEQ * QKV_LD + C_DIM + h * D_HEAD;  // k
    float* C = g_scores + (size_t)z * N_SEQ * N_SEQ;

    __shared__ float As[16][128];
    __shared__ float Bs[16][128];
    const int tid = threadIdx.x;
    const int tx = tid & 15, ty = tid >> 4;
    const int row0 = blockIdx.y * 128;  // n
    const int col0 = blockIdx.x * 128;  // m

    float acc[8][8];
#pragma unroll
    for (int i = 0; i < 8; i++)
#pragma unroll
        for (int j = 0; j < 8; j++) acc[i][j] = 0.f;

#pragma unroll
    for (int k0 = 0; k0 < D_HEAD; k0 += 16) {
#pragma unroll
        for (int l = 0; l < 2; l++) {
            int f = tid + l * 256;
            int r = f >> 2;
            int cv = (f & 3) << 2;
            float4 v = *reinterpret_cast<const float4*>(Aq + (size_t)(row0 + r) * QKV_LD + k0 + cv);
            As[cv + 0][r] = v.x; As[cv + 1][r] = v.y; As[cv + 2][r] = v.z; As[cv + 3][r] = v.w;
            float4 w = *reinterpret_cast<const float4*>(Bk + (size_t)(col0 + r) * QKV_LD + k0 + cv);
            Bs[cv + 0][r] = w.x; Bs[cv + 1][r] = w.y; Bs[cv + 2][r] = w.z; Bs[cv + 3][r] = w.w;
        }
        __syncthreads();
#pragma unroll
        for (int k = 0; k < 16; k++) {
            float4 a0 = *reinterpret_cast<const float4*>(&As[k][ty * 8]);
            float4 a1 = *reinterpret_cast<const float4*>(&As[k][ty * 8 + 4]);
            float4 b0 = *reinterpret_cast<const float4*>(&Bs[k][tx * 8]);
            float4 b1 = *reinterpret_cast<const float4*>(&Bs[k][tx * 8 + 4]);
            float a[8] = {a0.x, a0.y, a0.z, a0.w, a1.x, a1.y, a1.z, a1.w};
            float b[8] = {b0.x, b0.y, b0.z, b0.w, b1.x, b1.y, b1.z, b1.w};
#pragma unroll
            for (int i = 0; i < 8; i++)
#pragma unroll
                for (int j = 0; j < 8; j++) acc[i][j] = fmaf(a[i], b[j], acc[i][j]);
        }
        __syncthreads();
    }
#pragma unroll
    for (int i = 0; i < 8; i++) {
        int r = row0 + ty * 8 + i;
#pragma unroll
        for (int j = 0; j < 8; j++) {
            C[(size_t)r * N_SEQ + col0 + tx * 8 + j] = acc[i][j] * SCALE;
        }
    }
}

// ---------------------------------------------------------------------------
// Fused pre-mix (w_l) -> softmax over m -> post-mix (w_w), in-place on scores.
// One CTA per (b, n); thread t owns columns m = 4t..4t+3 for all 12 heads.
// ---------------------------------------------------------------------------
__global__ __launch_bounds__(256) void mixsoftmax_kernel(
    const float* __restrict__ w_l, const float* __restrict__ b_l,
    const float* __restrict__ w_w, const float* __restrict__ b_w)
{
    __shared__ float swl[144], sww[144], sbl[12], sbw[12];
    __shared__ float red[8][12];
    const int tid = threadIdx.x;
    if (tid < 144) { swl[tid] = w_l[tid]; sww[tid] = w_w[tid]; }
    if (tid < 12)  { sbl[tid] = b_l[tid]; sbw[tid] = b_w[tid]; }
    __syncthreads();

    const int bn = blockIdx.x;
    const int b = bn >> 10, n = bn & 1023;
    const size_t base = ((size_t)b * H_HEAD * N_SEQ + n) * N_SEQ;  // + h * N_SEQ*N_SEQ
    const int m0 = tid * 4;
    const int lane = tid & 31, wid = tid >> 5;

    // pre-mix: t[g][c] = b_l[g] + sum_h s[h][m] * w_l[h,g]
    float t[12][4];
#pragma unroll
    for (int g = 0; g < 12; g++) {
        float bl = sbl[g];
        t[g][0] = bl; t[g][1] = bl; t[g][2] = bl; t[g][3] = bl;
    }
#pragma unroll
    for (int h = 0; h < 12; h++) {
        float4 s4 = *reinterpret_cast<const float4*>(g_scores + base + (size_t)h * N_SEQ * N_SEQ + m0);
#pragma unroll
        for (int g = 0; g < 12; g++) {
            float wl = swl[h * 12 + g];
            t[g][0] = fmaf(s4.x, wl, t[g][0]);
            t[g][1] = fmaf(s4.y, wl, t[g][1]);
            t[g][2] = fmaf(s4.z, wl, t[g][2]);
            t[g][3] = fmaf(s4.w, wl, t[g][3]);
        }
    }

    // row max per g (block reduce over 1024 columns)
    float lmax[12];
#pragma unroll
    for (int g = 0; g < 12; g++) {
        float v = fmaxf(fmaxf(t[g][0], t[g][1]), fmaxf(t[g][2], t[g][3]));
#pragma unroll
        for (int o = 16; o > 0; o >>= 1) v = fmaxf(v, __shfl_xor_sync(0xffffffffu, v, o));
        if (lane == 0) red[wid][g] = v;
    }
    __syncthreads();
#pragma unroll
    for (int g = 0; g < 12; g++) {
        float v = red[0][g];
#pragma unroll
        for (int w = 1; w < 8; w++) v = fmaxf(v, red[w][g]);
        lmax[g] = v;
    }
    __syncthreads();

    // exp + row sum
    float lsum[12];
#pragma unroll
    for (int g = 0; g < 12; g++) {
        t[g][0] = __expf(t[g][0] - lmax[g]);
        t[g][1] = __expf(t[g][1] - lmax[g]);
        t[g][2] = __expf(t[g][2] - lmax[g]);
        t[g][3] = __expf(t[g][3] - lmax[g]);
        float v = (t[g][0] + t[g][1]) + (t[g][2] + t[g][3]);
#pragma unroll
        for (int o = 16; o > 0; o >>= 1) v += __shfl_xor_sync(0xffffffffu, v, o);
        if (lane == 0) red[wid][g] = v;
    }
    __syncthreads();
#pragma unroll
    for (int g = 0; g < 12; g++) {
        float v = red[0][g];
#pragma unroll
        for (int w = 1; w < 8; w++) v += red[w][g];
        lsum[g] = 1.0f / v;
    }

    // normalize
#pragma unroll
    for (int g = 0; g < 12; g++) {
        t[g][0] *= lsum[g]; t[g][1] *= lsum[g]; t[g][2] *= lsum[g]; t[g][3] *= lsum[g];
    }

    // post-mix + in-place write (thread only touches its own columns: safe)
#pragma unroll
    for (int g = 0; g < 12; g++) {
        float o0 = sbw[g], o1 = sbw[g], o2 = sbw[g], o3 = sbw[g];
#pragma unroll
        for (int h = 0; h < 12; h++) {
            float ww = sww[h * 12 + g];
            o0 = fmaf(t[h][0], ww, o0);
            o1 = fmaf(t[h][1], ww, o1);
            o2 = fmaf(t[h][2], ww, o2);
            o3 = fmaf(t[h][3], ww, o3);
        }
        float4 out4 = make_float4(o0, o1, o2, o3);
        *reinterpret_cast<float4*>(g_scores + base + (size_t)g * N_SEQ * N_SEQ + m0) = out4;
    }
}

// ---------------------------------------------------------------------------
// AV: av[b, n, h*64+d] = sum_m attn[z, n, m] * v[z, m, d], z = b*12+h
// 128x64 block, BK=16, 256 threads, 8x4 per thread. K=1024.
// ---------------------------------------------------------------------------
__global__ __launch_bounds__(256) void av_kernel()
{
    const int z = blockIdx.z;
    const int b = z / H_HEAD, h = z % H_HEAD;
    const float* A  = g_scores + (size_t)z * N_SEQ * N_SEQ;
    const float* Bv = g_qkv + (size_t)b * N_SEQ * QKV_LD + 2 * C_DIM + h * D_HEAD;
    float* C = g_av + (size_t)b * N_SEQ * C_DIM + h * D_HEAD;

    __shared__ float As[16][128];
    __shared__ float Bs[16][64];
    const int tid = threadIdx.x;
    const int tx = tid & 15, ty = tid >> 4;
    const int row0 = blockIdx.y * 128;

    float acc[8][4];
#pragma unroll
    for (int i = 0; i < 8; i++)
#pragma unroll
        for (int j = 0; j < 4; j++) acc[i][j] = 0.f;

    for (int k0 = 0; k0 < N_SEQ; k0 += 16) {
#pragma unroll
        for (int l = 0; l < 2; l++) {
            int f = tid + l * 256;
            int r = f >> 2;
            int cv = (f & 3) << 2;
            float4 v = *reinterpret_cast<const float4*>(A + (size_t)(row0 + r) * N_SEQ + k0 + cv);
            As[cv + 0][r] = v.x; As[cv + 1][r] = v.y; As[cv + 2][r] = v.z; As[cv + 3][r] = v.w;
        }
        {
            int r = tid >> 4;
            int cv = (tid & 15) << 2;
            *reinterpret_cast<float4*>(&Bs[r][cv]) =
                *reinterpret_cast<const float4*>(Bv + (size_t)(k0 + r) * QKV_LD + cv);
        }
        __syncthreads();
#pragma unroll
        for (int k = 0; k < 16; k++) {
            float4 a0 = *reinterpret_cast<const float4*>(&As[k][ty * 8]);
            float4 a1 = *reinterpret_cast<const float4*>(&As[k][ty * 8 + 4]);
            float4 bq = *reinterpret_cast<const float4*>(&Bs[k][tx * 4]);
            float a[8] = {a0.x, a0.y, a0.z, a0.w, a1.x, a1.y, a1.z, a1.w};
            float bb[4] = {bq.x, bq.y, bq.z, bq.w};
#pragma unroll
            for (int i = 0; i < 8; i++)
#pragma unroll
                for (int j = 0; j < 4; j++) acc[i][j] = fmaf(a[i], bb[j], acc[i][j]);
        }
        __syncthreads();
    }
#pragma unroll
    for (int i = 0; i < 8; i++) {
        int r = row0 + ty * 8 + i;
#pragma unroll
        for (int j = 0; j < 4; j++) {
            C[(size_t)r * C_DIM + tx * 4 + j] = acc[i][j];
        }
    }
}

// ---------------------------------------------------------------------------
extern "C" void kernel_launch(void* const* d_in, const int* in_sizes, int n_in,
                              void* d_out, int out_size)
{
    const float* x      = (const float*)d_in[0];
    const float* w_qkv  = (const float*)d_in[1];
    const float* b_qkv  = (const float*)d_in[2];
    const float* w_l    = (const float*)d_in[3];
    const float* b_l    = (const float*)d_in[4];
    const float* w_w    = (const float*)d_in[5];
    const float* b_w    = (const float*)d_in[6];
    const float* w_proj = (const float*)d_in[7];
    const float* b_proj = (const float*)d_in[8];
    float* out = (float*)d_out;

    float *qkv_p = nullptr, *av_p = nullptr;
    cudaGetSymbolAddress((void**)&qkv_p, g_qkv);
    cudaGetSymbolAddress((void**)&av_p, g_av);

    dim3 blk(256);

    // 1) QKV projection: [8192,768] @ [768,2304] + bias
    gemm_nn_bias<<<dim3(3 * C_DIM / 128, B_SZ * N_SEQ / 128), blk>>>(
        x, w_qkv, b_qkv, qkv_p, C_DIM, C_DIM, QKV_LD, QKV_LD);

    // 2) scores = SCALE * q @ k^T per (b,h)
    qk_kernel<<<dim3(N_SEQ / 128, N_SEQ / 128, B_SZ * H_HEAD), blk>>>();

    // 3) fused talking-heads pre-mix + softmax + post-mix (in place)
    mixsoftmax_kernel<<<B_SZ * N_SEQ, 256>>>(w_l, b_l, w_w, b_w);

    // 4) av = attn @ v, written as [b, n, h*64+d]
    av_kernel<<<dim3(1, N_SEQ / 128, B_SZ * H_HEAD), blk>>>();

    // 5) out = av @ w_proj + b_proj
    gemm_nn_bias<<<dim3(C_DIM / 128, B_SZ * N_SEQ / 128), blk>>>(
        av_p, w_proj, b_proj, out, C_DIM, C_DIM, C_DIM, C_DIM);
}